// round 6
// baseline (speedup 1.0000x reference)
#include <cuda_runtime.h>
#include <cuda_bf16.h>

// AccumulateLoss: P=10 pose pairs, B batch. 10 triples (i<k<j) over CONTINLEN=5.
// loss = 50 * sum||R1@R2 - R12||^2 + sum||R1@t1 + t2 - t12||^2
//
// pair ids: (0,1)=0 (0,2)=1 (0,3)=2 (0,4)=3 (1,2)=4 (1,3)=5 (1,4)=6 (2,3)=7 (2,4)=8 (3,4)=9
// triples (i1,i2,i12) in module order:
//  (0,4,1)(0,5,2)(1,7,2)(0,6,3)(1,8,3)(2,9,3)(4,7,5)(4,8,6)(5,9,6)(7,9,8)

#define NPAIRS 10
#define BPB 64                 // batch elements (and threads) per block

__global__ void hx_init_out(float* out) {
    if (threadIdx.x == 0) out[0] = 0.0f;
}

__global__ void __launch_bounds__(BPB)
hx_accum_loss(const float* __restrict__ rotas,
              const float* __restrict__ transs,
              float* __restrict__ out, int B)
{
    // Staging: per pair, 64 batch elems * 9 rot floats and * 3 trans floats.
    __shared__ float Rs[NPAIRS * BPB * 9];   // 5760 floats
    __shared__ float Ts[NPAIRS * BPB * 3];   // 1920 floats
    __shared__ float red[2][2];

    const int tid = threadIdx.x;
    const size_t b0 = (size_t)blockIdx.x * BPB;

    // ---- cooperative, fully coalesced float4 staging (gmem -> smem) ----
    // rot chunk per pair: 64*9 floats = 144 float4 (base offset divisible by 16B:
    // (p*B + b0)*9*4 with b0 % 64 == 0). trans chunk: 64*3 = 48 float4.
#pragma unroll
    for (int p = 0; p < NPAIRS; p++) {
        const float4* r4 = reinterpret_cast<const float4*>(rotas + ((size_t)p * B + b0) * 9);
        float4* rs4 = reinterpret_cast<float4*>(&Rs[p * (BPB * 9)]);
        rs4[tid]       = r4[tid];
        rs4[tid + 64]  = r4[tid + 64];
        if (tid < 16) rs4[tid + 128] = r4[tid + 128];

        const float4* t4 = reinterpret_cast<const float4*>(transs + ((size_t)p * B + b0) * 3);
        float4* ts4 = reinterpret_cast<float4*>(&Ts[p * (BPB * 3)]);
        if (tid < 48) ts4[tid] = t4[tid];
    }
    __syncthreads();

    // ---- per-thread: pull my 120 floats into registers (stride-9/3 LDS, conflict-free) ----
    float R[NPAIRS][9];
    float T[NPAIRS][3];
#pragma unroll
    for (int p = 0; p < NPAIRS; p++) {
        const float* rp = &Rs[p * (BPB * 9) + tid * 9];
#pragma unroll
        for (int e = 0; e < 9; e++) R[p][e] = rp[e];
        const float* tp = &Ts[p * (BPB * 3) + tid * 3];
#pragma unroll
        for (int e = 0; e < 3; e++) T[p][e] = tp[e];
    }

    float rs = 0.0f, ts = 0.0f;

    // All indices compile-time -> pure register math, no dynamic indexing.
#define TRIPLE(P1, P2, P12)                                                       \
    {                                                                             \
        _Pragma("unroll")                                                         \
        for (int i = 0; i < 3; i++) {                                             \
            _Pragma("unroll")                                                     \
            for (int j = 0; j < 3; j++) {                                         \
                float f = R[P1][i*3+0] * R[P2][0*3+j]                             \
                        + R[P1][i*3+1] * R[P2][1*3+j]                             \
                        + R[P1][i*3+2] * R[P2][2*3+j];                            \
                float d = f - R[P12][i*3+j];                                      \
                rs += d * d;                                                      \
            }                                                                     \
            float g = R[P1][i*3+0] * T[P1][0]                                     \
                    + R[P1][i*3+1] * T[P1][1]                                     \
                    + R[P1][i*3+2] * T[P1][2] + T[P2][i];                         \
            float dg = g - T[P12][i];                                             \
            ts += dg * dg;                                                        \
        }                                                                         \
    }

    TRIPLE(0, 4, 1)
    TRIPLE(0, 5, 2)
    TRIPLE(1, 7, 2)
    TRIPLE(0, 6, 3)
    TRIPLE(1, 8, 3)
    TRIPLE(2, 9, 3)
    TRIPLE(4, 7, 5)
    TRIPLE(4, 8, 6)
    TRIPLE(5, 9, 6)
    TRIPLE(7, 9, 8)
#undef TRIPLE

    // ---- reduction: warp shfl -> 2-warp smem -> one atomicAdd per block ----
#pragma unroll
    for (int o = 16; o > 0; o >>= 1) {
        rs += __shfl_down_sync(0xffffffffu, rs, o);
        ts += __shfl_down_sync(0xffffffffu, ts, o);
    }
    const int wid = tid >> 5;
    if ((tid & 31) == 0) { red[0][wid] = rs; red[1][wid] = ts; }
    __syncthreads();
    if (tid == 0) {
        float a = red[0][0] + red[0][1];
        float b = red[1][0] + red[1][1];
        atomicAdd(out, 50.0f * a + b);
    }
}

extern "C" void kernel_launch(void* const* d_in, const int* in_sizes, int n_in,
                              void* d_out, int out_size)
{
    const float* rotas  = (const float*)d_in[0];   // [10, B, 3, 3] fp32
    const float* transs = (const float*)d_in[1];   // [10, B, 3]    fp32
    float* out = (float*)d_out;                    // [1] fp32 (poisoned -> init)

    const int B = in_sizes[0] / (NPAIRS * 9);      // 262144

    hx_init_out<<<1, 32>>>(out);
    hx_accum_loss<<<B / BPB, BPB>>>(rotas, transs, out, B);
}

// round 8
// speedup vs baseline: 1.2409x; 1.2409x over previous
#include <cuda_runtime.h>
#include <cstdint>

// AccumulateLoss: P=10 pose pairs, B batch. 10 triples (i<k<j) over CONTINLEN=5.
// loss = 50 * sum||R1@R2 - R12||^2 + sum||R1@t1 + t2 - t12||^2
// DRAM-bound (126MB / ~7TB/s ~ 18us). Strategy: persistent blocks, double-buffered
// cp.async.bulk (TMA bulk) gmem->smem pipeline so DRAM streams continuously instead
// of phase-locked load/compute waves.

#define NPAIRS 10
#define TILE   64                         // batch elems per tile (= threads/block)
#define BPB    64
#define RFLOATS (NPAIRS * TILE * 9)       // 5760 floats per buffer (rot)
#define TFLOATS (NPAIRS * TILE * 3)       // 1920 floats per buffer (trans)
#define BUF_FLOATS (RFLOATS + TFLOATS)    // 7680
#define BUF_BYTES  (BUF_FLOATS * 4)       // 30720
#define NBLOCKS 456                       // 3 per SM on 152-SM GB300

__global__ void hx_init_out(float* out) {
    if (threadIdx.x == 0) out[0] = 0.0f;
}

__device__ __forceinline__ uint32_t smem_u32(const void* p) {
    return (uint32_t)__cvta_generic_to_shared(p);
}
__device__ __forceinline__ void mbar_init(uint32_t a, uint32_t cnt) {
    asm volatile("mbarrier.init.shared.b64 [%0], %1;" :: "r"(a), "r"(cnt) : "memory");
}
__device__ __forceinline__ void mbar_expect_tx(uint32_t a, uint32_t bytes) {
    asm volatile("mbarrier.arrive.expect_tx.shared.b64 _, [%0], %1;"
                 :: "r"(a), "r"(bytes) : "memory");
}
__device__ __forceinline__ void mbar_wait(uint32_t a, uint32_t parity) {
    asm volatile(
        "{\n\t.reg .pred P;\n\t"
        "WAIT_LOOP_%=:\n\t"
        "mbarrier.try_wait.parity.acquire.cta.shared::cta.b64 P, [%0], %1, 0x989680;\n\t"
        "@P bra.uni WAIT_DONE_%=;\n\t"
        "bra.uni WAIT_LOOP_%=;\n\t"
        "WAIT_DONE_%=:\n\t}"
        :: "r"(a), "r"(parity) : "memory");
}
__device__ __forceinline__ void bulk_g2s(uint32_t dst, const void* src,
                                         uint32_t bytes, uint32_t mbar) {
    asm volatile(
        "cp.async.bulk.shared::cluster.global.mbarrier::complete_tx::bytes "
        "[%0], [%1], %2, [%3];"
        :: "r"(dst), "l"(src), "r"(bytes), "r"(mbar) : "memory");
}

// Issue the 20 bulk copies for one tile into buffer `base` (thread 0 only).
__device__ __forceinline__ void prefetch_tile(const float* __restrict__ rotas,
                                              const float* __restrict__ transs,
                                              int B, int tile,
                                              float* base, uint32_t mb) {
    mbar_expect_tx(mb, BUF_BYTES);
#pragma unroll
    for (int p = 0; p < NPAIRS; p++) {
        bulk_g2s(smem_u32(base + p * (TILE * 9)),
                 rotas + ((size_t)p * B + (size_t)tile * TILE) * 9,
                 TILE * 9 * 4, mb);
        bulk_g2s(smem_u32(base + RFLOATS + p * (TILE * 3)),
                 transs + ((size_t)p * B + (size_t)tile * TILE) * 3,
                 TILE * 3 * 4, mb);
    }
}

extern __shared__ float sbuf[];   // 2 * BUF_FLOATS floats (61440 bytes)

__global__ void __launch_bounds__(BPB)
hx_accum_loss(const float* __restrict__ rotas,
              const float* __restrict__ transs,
              float* __restrict__ out, int B)
{
    __shared__ __align__(8) unsigned long long mbar[2];
    __shared__ float red[2][2];

    const int tid = threadIdx.x;
    const int ntiles = B / TILE;
    const int stride = gridDim.x;

    if (tid == 0) {
        mbar_init(smem_u32(&mbar[0]), 1);
        mbar_init(smem_u32(&mbar[1]), 1);
        asm volatile("fence.proxy.async.shared::cta;" ::: "memory");
    }
    __syncthreads();

    // Prologue: prefetch first two tiles for this block.
    const int t0 = blockIdx.x;
    if (tid == 0) {
        if (t0 < ntiles)
            prefetch_tile(rotas, transs, B, t0, sbuf, smem_u32(&mbar[0]));
        if (t0 + stride < ntiles)
            prefetch_tile(rotas, transs, B, t0 + stride,
                          sbuf + BUF_FLOATS, smem_u32(&mbar[1]));
    }

    float rsa[4] = {0.f, 0.f, 0.f, 0.f};
    float tsa[2] = {0.f, 0.f};

    int ph0 = 0, ph1 = 0;
    int m = 0;
    for (int tile = t0; tile < ntiles; tile += stride, m++) {
        const int buf = m & 1;
        float* base = sbuf + buf * BUF_FLOATS;

        if (buf == 0) { mbar_wait(smem_u32(&mbar[0]), ph0); ph0 ^= 1; }
        else          { mbar_wait(smem_u32(&mbar[1]), ph1); ph1 ^= 1; }

        // Pull my 120 floats smem -> regs (stride-9 / stride-3 LDS, conflict-free).
        float R[NPAIRS][9];
        float T[NPAIRS][3];
#pragma unroll
        for (int p = 0; p < NPAIRS; p++) {
            const float* rp = base + p * (TILE * 9) + tid * 9;
#pragma unroll
            for (int e = 0; e < 9; e++) R[p][e] = rp[e];
            const float* tp = base + RFLOATS + p * (TILE * 3) + tid * 3;
#pragma unroll
            for (int e = 0; e < 3; e++) T[p][e] = tp[e];
        }
        __syncthreads();   // everyone done reading this buffer

        // Refill this buffer with tile m+2 while we compute tile m.
        const int nxt = tile + 2 * stride;
        if (tid == 0 && nxt < ntiles)
            prefetch_tile(rotas, transs, B, nxt, base, smem_u32(&mbar[buf]));

        // ---- compute: all indices compile-time; split accumulators break chains ----
#define TRIPLE(P1, P2, P12)                                                    \
        {                                                                      \
            _Pragma("unroll")                                                  \
            for (int i = 0; i < 3; i++) {                                      \
                _Pragma("unroll")                                              \
                for (int j = 0; j < 3; j++) {                                  \
                    float f = R[P1][i*3+0] * R[P2][0*3+j]                      \
                            + R[P1][i*3+1] * R[P2][1*3+j]                      \
                            + R[P1][i*3+2] * R[P2][2*3+j];                     \
                    float d = f - R[P12][i*3+j];                               \
                    rsa[(i*3+j) & 3] += d * d;                                 \
                }                                                              \
                float g = R[P1][i*3+0] * T[P1][0]                              \
                        + R[P1][i*3+1] * T[P1][1]                              \
                        + R[P1][i*3+2] * T[P1][2] + T[P2][i];                  \
                float dg = g - T[P12][i];                                      \
                tsa[i & 1] += dg * dg;                                         \
            }                                                                  \
        }

        TRIPLE(0, 4, 1)
        TRIPLE(0, 5, 2)
        TRIPLE(1, 7, 2)
        TRIPLE(0, 6, 3)
        TRIPLE(1, 8, 3)
        TRIPLE(2, 9, 3)
        TRIPLE(4, 7, 5)
        TRIPLE(4, 8, 6)
        TRIPLE(5, 9, 6)
        TRIPLE(7, 9, 8)
#undef TRIPLE
    }

    // ---- reduction: warp shfl -> 2-warp smem -> one atomicAdd per block ----
    float rs = (rsa[0] + rsa[1]) + (rsa[2] + rsa[3]);
    float ts = tsa[0] + tsa[1];
#pragma unroll
    for (int o = 16; o > 0; o >>= 1) {
        rs += __shfl_down_sync(0xffffffffu, rs, o);
        ts += __shfl_down_sync(0xffffffffu, ts, o);
    }
    const int wid = tid >> 5;
    if ((tid & 31) == 0) { red[0][wid] = rs; red[1][wid] = ts; }
    __syncthreads();
    if (tid == 0) {
        float a = red[0][0] + red[0][1];
        float b = red[1][0] + red[1][1];
        atomicAdd(out, 50.0f * a + b);
    }
}

extern "C" void kernel_launch(void* const* d_in, const int* in_sizes, int n_in,
                              void* d_out, int out_size)
{
    const float* rotas  = (const float*)d_in[0];   // [10, B, 3, 3] fp32
    const float* transs = (const float*)d_in[1];   // [10, B, 3]    fp32
    float* out = (float*)d_out;                    // [1] fp32 (poisoned -> init)

    const int B = in_sizes[0] / (NPAIRS * 9);      // 262144
    const int ntiles = B / TILE;                   // 4096
    const int grid = ntiles < NBLOCKS ? ntiles : NBLOCKS;

    static int attr_set = 0;
    if (!attr_set) {
        cudaFuncSetAttribute(hx_accum_loss,
                             cudaFuncAttributeMaxDynamicSharedMemorySize,
                             2 * BUF_BYTES);
        attr_set = 1;
    }

    hx_init_out<<<1, 32>>>(out);
    hx_accum_loss<<<grid, BPB, 2 * BUF_BYTES>>>(rotas, transs, out, B);
}